// round 15
// baseline (speedup 1.0000x reference)
#include <cuda_runtime.h>
#include <cuda_bf16.h>
#include <mma.h>

// Problem sizes (fixed by the dataset)
#define NN 65536
#define DD 32
#define HH 1024
#define CC 64

#define NTILES   (NN / 32)     // 2048 row-tiles of 32 rows
#define PGRID    148           // persistent grid: one CTA per SM

// Triangular staged-weight layout (see k_main):
//   sw2 region: sum_d L(d)      = 16399 float2  (L(d)=33d+1, L(0)=0)
//   sw1 region: sum_d (1024-L)  = 16369 float
//   sx  region: 8 warps x 4 rows x 33 floats (padded x tile)
#define SW2_F2   16399
#define SW1_F    16369
#define SW2_BYTES (SW2_F2 * 8)
#define SX_OFF   (SW2_BYTES + SW1_F * 4)
#define SMEM_MAIN_BYTES (SX_OFF + 8 * 4 * 33 * 4)   // 200,892 B < 228 KB

// Degree-sorted unit layout: deg(h) = h % 31 + 1; sorted prefix 33g+1 holds
// exactly units deg<=g. perm(j) = original unit index of sorted slot j.
__device__ __forceinline__ int perm_unit(int j) {
    int g, k;
    if (j < 34) { g = 1; k = j; }
    else        { g = (j - 1) / 33 + 1; k = j - (33 * (g - 1) + 1); }
    return (g - 1) + 31 * k;
}

// Fast tanh: 1 - 2/(1+e^{2x}); abs err ~1e-6, saturates correctly.
__device__ __forceinline__ float tanh_fast(float v) {
    float e, r;
    asm("ex2.approx.f32 %0, %1;" : "=f"(e) : "f"(v * 2.885390081777927f)); // 2*log2(e)
    asm("rcp.approx.f32 %0, %1;" : "=f"(r) : "f"(e + 1.0f));
    return fmaf(-2.0f, r, 1.0f);
}

// Packed f32x2 helpers (Blackwell FFMA2 — PTX-only path).
__device__ __forceinline__ unsigned long long pk(float lo, float hi) {
    unsigned long long u;
    asm("mov.b64 %0, {%1, %2};" : "=l"(u) : "f"(lo), "f"(hi));
    return u;
}
__device__ __forceinline__ void upk(unsigned long long u, float& lo, float& hi) {
    asm("mov.b64 {%0, %1}, %2;" : "=f"(lo), "=f"(hi) : "l"(u));
}
__device__ __forceinline__ unsigned long long fma2(unsigned long long a,
                                                   unsigned long long b,
                                                   unsigned long long c) {
    unsigned long long d;
    asm("fma.rn.f32x2 %0, %1, %2, %3;" : "=l"(d) : "l"(a), "l"(b), "l"(c));
    return d;
}

// Scratch (device globals: allocation-free per harness rules)
__device__ float  g_pre[(size_t)NN * HH];   // 256 MB: context@Wc + b1 (permuted cols)
__device__ float  g_W1p[DD * HH];           // W1p[d][j] = W1[d][perm(j)]
__device__ float2 g_W2p[DD * HH];           // W2p[d][j] = W2[perm(j)][d][0..1]
__device__ float  g_Wcp[CC * HH];           // Wcp[c][j] = Wc[c][perm(j)]
__device__ float  g_b1p[HH];

// ---------------------------------------------------------------------------
// Kernel 1: permute weights into degree-sorted order
// ---------------------------------------------------------------------------
__global__ void k_permute(const float* __restrict__ W1, const float* __restrict__ b1,
                          const float* __restrict__ Wc, const float* __restrict__ W2) {
    int j = blockIdx.x * blockDim.x + threadIdx.x;
    if (j >= HH) return;
    int h = perm_unit(j);
    g_b1p[j] = b1[h];
#pragma unroll
    for (int d = 0; d < DD; d++) g_W1p[d * HH + j] = W1[d * HH + h];
#pragma unroll
    for (int c = 0; c < CC; c++) g_Wcp[c * HH + j] = Wc[c * HH + h];
#pragma unroll
    for (int d = 0; d < DD; d++)
        g_W2p[d * HH + j] = make_float2(W2[h * (DD * 2) + d * 2 + 0],
                                        W2[h * (DD * 2) + d * 2 + 1]);
}

// ---------------------------------------------------------------------------
// Kernel 2: pre[n][j] = ctx[n]@Wcp[:,j] + b1p[j]. tf32x3 wmma, fp32 accum.
// V2: 512 blocks x 256 thr; block = 128 rows x ALL 1024 cols. B tile (16KB)
// staged in SHARED per col-group (wmma reads smem, not strided global); A
// frags reused 16x from L1. Per-fragment smem epilogue, sector-aligned STG.
// ---------------------------------------------------------------------------
__global__ __launch_bounds__(256)
void k_pregemm(const float* __restrict__ ctx) {
    using namespace nvcuda;
    __shared__ float sB[64 * 64];          // 16 KB: B tile (K=64 x 64 cols)
    __shared__ float tw_all[8][256];       // 8 KB: per-warp 16x16 epilogue staging

    const int warpId = threadIdx.x >> 5;
    const int lane   = threadIdx.x & 31;
    const int row0   = blockIdx.x * 128 + warpId * 16;
    const float* Aptr = ctx + (size_t)row0 * CC;
    float* tw = tw_all[warpId];

    for (int ct = 0; ct < 16; ct++) {
        __syncthreads();   // all warps done reading previous sB
        for (int i = threadIdx.x; i < 64 * 16; i += 256) {      // 1024 float4s
            int c = i >> 4, ch = i & 15;
            *reinterpret_cast<float4*>(sB + c * 64 + ch * 4) =
                *reinterpret_cast<const float4*>(g_Wcp + c * HH + ct * 64 + ch * 4);
        }
        __syncthreads();

        wmma::fragment<wmma::accumulator, 16, 16, 8, float> acc[4];
#pragma unroll
        for (int c = 0; c < 4; c++) wmma::fill_fragment(acc[c], 0.0f);

#pragma unroll
        for (int kk = 0; kk < 8; kk++) {
            wmma::fragment<wmma::matrix_a, 16, 16, 8, wmma::precision::tf32, wmma::row_major> aHi, aLo;
            wmma::load_matrix_sync(aHi, Aptr + kk * 8, CC);
#pragma unroll
            for (int t = 0; t < aHi.num_elements; t++) {
                float f  = aHi.x[t];
                float hi = wmma::__float_to_tf32(f);
                aHi.x[t] = hi;
                aLo.x[t] = wmma::__float_to_tf32(f - hi);
            }
#pragma unroll
            for (int c = 0; c < 4; c++) {
                wmma::fragment<wmma::matrix_b, 16, 16, 8, wmma::precision::tf32, wmma::row_major> bHi, bLo;
                wmma::load_matrix_sync(bHi, sB + kk * 8 * 64 + c * 16, 64);
#pragma unroll
                for (int t = 0; t < bHi.num_elements; t++) {
                    float f  = bHi.x[t];
                    float hi = wmma::__float_to_tf32(f);
                    bHi.x[t] = hi;
                    bLo.x[t] = wmma::__float_to_tf32(f - hi);
                }
                wmma::mma_sync(acc[c], aHi, bHi, acc[c]);
                wmma::mma_sync(acc[c], aLo, bHi, acc[c]);
                wmma::mma_sync(acc[c], aHi, bLo, acc[c]);
            }
        }

        // epilogue: per 16x16 fragment via warp-private smem staging
#pragma unroll
        for (int c = 0; c < 4; c++) {
            wmma::store_matrix_sync(tw, acc[c], 16, wmma::mem_row_major);
            __syncwarp();
            for (int i = lane; i < 256; i += 32) {
                int r = i >> 4, cc = i & 15;
                int col = ct * 64 + c * 16 + cc;
                g_pre[(size_t)(row0 + r) * HH + col] = tw[i] + g_b1p[col];
            }
            __syncwarp();
        }
    }
}

// ---------------------------------------------------------------------------
// Capture-index shim: keeps ncu's -s 5 -c 1 capture landing on k_main.
// ---------------------------------------------------------------------------
__global__ void k_shim() {}

// ---------------------------------------------------------------------------
// Kernel 3: PERSISTENT sequential MADE sampling (grid=148, 1 CTA/SM).
// V2: state packed as f32x2 pairs (rows 0,1 / 2,3) -> FFMA2 halves MAC instrs;
// combined 8-value butterfly reduce-scatter (40 ops/step vs 80) with 1 exp
// per lane; x tile in padded smem for lane-group row access.
// ---------------------------------------------------------------------------
__global__ __launch_bounds__(256, 1)
void k_main(const float* __restrict__ x, const float* __restrict__ b2,
            float* __restrict__ out) {
    extern __shared__ char dynsmem[];
    float2* sm2 = (float2*)dynsmem;               // packed W2 prefixes
    float*  sm1 = (float*)(dynsmem + SW2_BYTES);  // packed W1 suffixes
    float*  sx  = (float*)(dynsmem + SX_OFF);     // x tiles, 33-padded

    const int tid = threadIdx.x;
    const int lane = tid & 31;
    const int warpId = tid >> 5;

    // -------- stage the full triangular weight set (ONCE per SM) --------
    {
        int o1 = 0, o2 = 0;
        for (int d = 0; d < DD; d++) {
            const int L = d ? 33 * d + 1 : 0;
            for (int i = tid; i < L; i += 256)      sm2[o2 + i] = g_W2p[d * HH + i];
            for (int i = tid; i < HH - L; i += 256) sm1[o1 + i] = g_W1p[d * HH + L + i];
            o2 += L; o1 += HH - L;
        }
    }
    const float b2s = b2[2 * lane + 0];
    const float b2l = b2[2 * lane + 1];
    float* sxw = sx + warpId * 132;               // warp-private x tile
    const int jmine = (lane >> 2) & 3;            // value-group row index
    const bool hi16 = (lane & 16) != 0;
    const bool hi8  = (lane & 8) != 0;
    const bool hi4  = (lane & 4) != 0;

    __syncthreads();   // staged weights visible; only block barrier

    // -------- persistent tile loop --------
    for (int t = blockIdx.x; t < NTILES; t += PGRID) {
        const int nb = t * 32 + warpId * 4;   // 4 consecutive rows per warp

        unsigned long long S01[32], S23[32];  // packed state (r0,r1),(r2,r3)
        float yacc[4];
        float ld_mine = 0.f;
        {
            const float* p0 = g_pre + (size_t)(nb + 0) * HH;
            const float* p1 = g_pre + (size_t)(nb + 1) * HH;
            const float* p2 = g_pre + (size_t)(nb + 2) * HH;
            const float* p3 = g_pre + (size_t)(nb + 3) * HH;
#pragma unroll
            for (int r = 0; r < 32; r++) {
                S01[r] = pk(p0[r * 32 + lane], p1[r * 32 + lane]);
                S23[r] = pk(p2[r * 32 + lane], p3[r * 32 + lane]);
            }
#pragma unroll
            for (int j = 0; j < 4; j++) {
                sxw[j * 33 + lane] = x[(nb + j) * DD + lane];
                yacc[j] = 0.f;
            }
            __syncwarp();
        }

        int o1 = 0, o2 = 0;
#pragma unroll
        for (int grp = 0; grp < 4; grp++) {
            const int R_RD  = 8 * (grp + 1);               // read slices [0, R_RD)
            const int R_UP  = 8 * grp;                     // update slices [R_UP, 32)
            const int FR_LO = (grp > 0) ? 8 * grp - 1 : 0; // static tanh band
            const int FR_HI = 8 * grp + 7;

#pragma unroll 1
            for (int dd = 0; dd < 8; dd++) {
                const int d   = grp * 8 + dd;
                const int L   = d ? 33 * d + 1 : 0;              // read set [0, L)
                const int fLo = (d >= 2) ? 33 * (d - 1) + 1 : 0; // freeze [fLo, L)
                const float2* w2s = sm2 + o2;                    // valid u in [0, L)
                const float*  w1s = sm1 + (o1 - L);              // valid u in [L, 1024)

                unsigned long long AS01 = 0ull, AS23 = 0ull, AL01 = 0ull, AL23 = 0ull;
#pragma unroll
                for (int r = 0; r < R_RD; r++) {
                    const int base = r * 32;
                    const int u = base + lane;
                    if (r >= FR_LO && r <= FR_HI) {           // static tanh band
                        if (base < L && base + 32 > fLo) {    // warp-uniform
                            if (u >= fLo && u < L) {
                                float a, b;
                                upk(S01[r], a, b); S01[r] = pk(tanh_fast(a), tanh_fast(b));
                                upk(S23[r], a, b); S23[r] = pk(tanh_fast(a), tanh_fast(b));
                            }
                        }
                    }
                    if (base < L) {                           // warp-uniform
                        float2 w = w2s[u];
                        if (u < L) {
                            unsigned long long wxx = pk(w.x, w.x);
                            unsigned long long wyy = pk(w.y, w.y);
                            AS01 = fma2(S01[r], wxx, AS01);
                            AS23 = fma2(S23[r], wxx, AS23);
                            AL01 = fma2(S01[r], wyy, AL01);
                            AL23 = fma2(S23[r], wyy, AL23);
                        }
                    }
                }
                // combined 8-value butterfly reduce-scatter:
                // bits {16,8,4} route value (as/al, row) to lane groups.
                float v0, v1, v2, v3, v4, v5, v6, v7;
                upk(AS01, v0, v1); upk(AS23, v2, v3);
                upk(AL01, v4, v5); upk(AL23, v6, v7);
                {   // level 16: keep as* (lo lanes) / al* (hi lanes)
                    float s0 = hi16 ? v0 : v4, s1 = hi16 ? v1 : v5;
                    float s2 = hi16 ? v2 : v6, s3 = hi16 ? v3 : v7;
                    v0 = (hi16 ? v4 : v0) + __shfl_xor_sync(~0u, s0, 16);
                    v1 = (hi16 ? v5 : v1) + __shfl_xor_sync(~0u, s1, 16);
                    v2 = (hi16 ? v6 : v2) + __shfl_xor_sync(~0u, s2, 16);
                    v3 = (hi16 ? v7 : v3) + __shfl_xor_sync(~0u, s3, 16);
                }
                {   // level 8: rows {0,1} vs {2,3}
                    float s0 = hi8 ? v0 : v2, s1 = hi8 ? v1 : v3;
                    v0 = (hi8 ? v2 : v0) + __shfl_xor_sync(~0u, s0, 8);
                    v1 = (hi8 ? v3 : v1) + __shfl_xor_sync(~0u, s1, 8);
                }
                {   // level 4: even vs odd row
                    float s0 = hi4 ? v0 : v1;
                    v0 = (hi4 ? v1 : v0) + __shfl_xor_sync(~0u, s0, 4);
                }
                v0 += __shfl_xor_sync(~0u, v0, 2);
                v0 += __shfl_xor_sync(~0u, v0, 1);
                const float pairv = __shfl_xor_sync(~0u, v0, 16);
                const float asj = hi16 ? pairv : v0;
                const float alj = hi16 ? v0 : pairv;

                const float sb = __shfl_sync(~0u, b2s, d);
                const float lb = __shfl_sync(~0u, b2l, d);
                const float ls = alj + lb;
                const float xd = sxw[jmine * 33 + d];
                const float yv_mine = fmaf(xd, __expf(ls), asj + sb);
                ld_mine += ls;

                const float yv0 = __shfl_sync(~0u, yv_mine, 0);
                const float yv1 = __shfl_sync(~0u, yv_mine, 4);
                const float yv2 = __shfl_sync(~0u, yv_mine, 8);
                const float yv3 = __shfl_sync(~0u, yv_mine, 12);
                if (lane == d) { yacc[0] = yv0; yacc[1] = yv1; yacc[2] = yv2; yacc[3] = yv3; }

                const unsigned long long YV01 = pk(yv0, yv1);
                const unsigned long long YV23 = pk(yv2, yv3);
#pragma unroll
                for (int r = R_UP; r < 32; r++) {
                    const int base = r * 32;
                    const int u = base + lane;
                    if (base + 32 > L) {                      // warp-uniform
                        float w = w1s[u];
                        if (u >= L) {
                            unsigned long long wp = pk(w, w);
                            S01[r] = fma2(YV01, wp, S01[r]);
                            S23[r] = fma2(YV23, wp, S23[r]);
                        }
                    }
                }
                o2 += L; o1 += HH - L;
            }
        }

        // outputs: y [N,D] then log_det [N]
#pragma unroll
        for (int j = 0; j < 4; j++)
            out[(size_t)(nb + j) * DD + lane] = yacc[j];
        if (lane < 16 && (lane & 3) == 0)
            out[(size_t)NN * DD + nb + (lane >> 2)] = ld_mine;
    }
}

// ---------------------------------------------------------------------------
extern "C" void kernel_launch(void* const* d_in, const int* in_sizes, int n_in,
                              void* d_out, int out_size) {
    const float* x   = (const float*)d_in[0];
    const float* ctx = (const float*)d_in[1];
    const float* W1  = (const float*)d_in[2];
    const float* b1  = (const float*)d_in[3];
    const float* Wc  = (const float*)d_in[4];
    const float* W2  = (const float*)d_in[5];
    const float* b2  = (const float*)d_in[6];
    float* out = (float*)d_out;

    // Host-side attribute set (not an allocation; idempotent, capture-safe).
    static int smem_set = 0;
    if (!smem_set) {
        cudaFuncSetAttribute(k_main, cudaFuncAttributeMaxDynamicSharedMemorySize,
                             SMEM_MAIN_BYTES);
        smem_set = 1;
    }

    k_permute<<<(HH + 127) / 128, 128>>>(W1, b1, Wc, W2);
    k_pregemm<<<NN / 128, 256>>>(ctx);            // 512 blocks x 8 warps
    k_shim<<<1, 32>>>();                          // keeps ncu capture on k_main
    k_main<<<PGRID, 256, SMEM_MAIN_BYTES>>>(x, b2, out);
}